// round 6
// baseline (speedup 1.0000x reference)
#include <cuda_runtime.h>
#include <cstdint>

#define S_LEN  128
#define B_SZ   32
#define E2D    1024
#define DHID   512
#define AHID   32
#define EMBD   256
#define VOCAB  32000
#define CATD   1536   // DH + E2  (W1 row length)
#define XDIM   1280   // E2 + EMB (W_ih row length)

// ---------------- device scratch (no allocation allowed) --------------------
__device__ __align__(16) float g_enc_proj[S_LEN * B_SZ * AHID]; // W1_enc@enc + b1
__device__ __align__(16) float g_h[B_SZ * DHID];                // hidden state
__device__ __align__(16) float g_x[B_SZ * XDIM];                // [ctx(1024) | emb(256)]
__device__ __align__(16) float g_gi[3 * DHID * B_SZ];           // layout [o][b]
__device__ __align__(16) float g_gh[3 * DHID * B_SZ];           // layout [o][b]
__device__ unsigned long long g_amax[B_SZ];

// ---------------- helpers ---------------------------------------------------
// monotone float -> u32 (order preserving over all finite floats)
__device__ __forceinline__ unsigned int fkey(float v) {
    unsigned int u = __float_as_uint(v);
    return (u & 0x80000000u) ? ~u : (u | 0x80000000u);
}
// pack so larger value wins; on equal value, LOWER index wins (jnp.argmax)
__device__ __forceinline__ unsigned long long packkey(float v, int idx) {
    return ((unsigned long long)fkey(v) << 32) |
           (unsigned long long)(0x7FFFFFFFu - (unsigned int)idx);
}

// ---------------- init: h=0, amax=0, x_emb = emb[sos] -----------------------
__global__ void k_init(const float* __restrict__ emb, const int* __restrict__ sos_p) {
    int i = blockIdx.x * blockDim.x + threadIdx.x;     // 16384 threads
    if (i < B_SZ * DHID) g_h[i] = 0.0f;
    if (i < B_SZ) g_amax[i] = 0ull;
    if (i < B_SZ * EMBD) {
        int sos = *sos_p;
        int b = i / EMBD, j = i % EMBD;
        g_x[b * XDIM + E2D + j] = emb[sos * EMBD + j];
    }
}

// ---------------- one-time: enc_proj[sb][a] = W1[a,512:]@enc[sb] + b1[a] ----
// grid 512 blocks (8 sb rows each), 256 threads
__global__ void k_encproj(const float* __restrict__ enc,
                          const float* __restrict__ W1,
                          const float* __restrict__ b1) {
    __shared__ float enc_sh[8 * E2D];   // 32 KB
    int tid = threadIdx.x;
    int sb0 = blockIdx.x * 8;
    for (int i = tid; i < 8 * E2D; i += 256)
        enc_sh[i] = enc[sb0 * E2D + i];
    __syncthreads();
    int a = tid & 31;
    int r = tid >> 5;                    // 0..7
    const float* w = W1 + a * CATD + DHID;
    const float* e = enc_sh + r * E2D;
    float a0 = 0.f, a1 = 0.f, a2 = 0.f, a3 = 0.f;
#pragma unroll 8
    for (int k = 0; k < E2D; k += 4) {
        a0 = fmaf(w[k],     e[k],     a0);
        a1 = fmaf(w[k + 1], e[k + 1], a1);
        a2 = fmaf(w[k + 2], e[k + 2], a2);
        a3 = fmaf(w[k + 3], e[k + 3], a3);
    }
    g_enc_proj[(sb0 + r) * AHID + a] = a0 + a1 + a2 + a3 + b1[a];
}

// ---------------- per-step attention: softmax + context -> g_x[:,0:1024] ----
// grid 32 blocks (one per batch), 256 threads
__global__ void k_attn(const float* __restrict__ enc,
                       const float* __restrict__ W1,
                       const float* __restrict__ W2,
                       const float* __restrict__ b2) {
    __shared__ float h_sh[DHID];
    __shared__ float part[8][AHID];
    __shared__ float hproj[AHID];
    __shared__ float sc[S_LEN];
    __shared__ float red[2];
    int tid = threadIdx.x;
    int b = blockIdx.x;

    for (int i = tid; i < DHID; i += 256) h_sh[i] = g_h[b * DHID + i];
    __syncthreads();

    // hproj[a] = W1[a,0:512] @ h  (8 segments x 32 a)
    {
        int a = tid & 31, seg = tid >> 5;
        const float* w = W1 + a * CATD + seg * 64;
        const float* hh = h_sh + seg * 64;
        float acc = 0.f;
#pragma unroll 8
        for (int k = 0; k < 64; k++) acc = fmaf(w[k], hh[k], acc);
        part[seg][a] = acc;
    }
    __syncthreads();
    if (tid < AHID) {
        float s = 0.f;
#pragma unroll
        for (int seg = 0; seg < 8; seg++) s += part[seg][tid];
        hproj[tid] = s;
    }
    __syncthreads();

    // scores over S
    if (tid < S_LEN) {
        const float* ep = g_enc_proj + (tid * B_SZ + b) * AHID;
        float sv = b2[0];
#pragma unroll
        for (int a = 0; a < AHID; a++) {
            float t = ep[a] + hproj[a];
            sv = fmaf(W2[a], fmaxf(t, 0.f), sv);
        }
        sc[tid] = sv;
    }
    __syncthreads();
    if (tid == 0) {
        float m = sc[0];
        for (int s = 1; s < S_LEN; s++) m = fmaxf(m, sc[s]);
        red[0] = m;
    }
    __syncthreads();
    if (tid < S_LEN) sc[tid] = expf(sc[tid] - red[0]);
    __syncthreads();
    if (tid == 0) {
        float su = 0.f;
        for (int s = 0; s < S_LEN; s++) su += sc[s];
        red[1] = 1.0f / su;
    }
    __syncthreads();
    if (tid < S_LEN) sc[tid] *= red[1];
    __syncthreads();

    // context: each thread 4 consecutive e via float4
    {
        float c0 = 0.f, c1 = 0.f, c2 = 0.f, c3 = 0.f;
        const float4* e4 = reinterpret_cast<const float4*>(enc);
        int col4 = (b * E2D) / 4 + tid;   // element offset /4 within row sb
#pragma unroll 4
        for (int s = 0; s < S_LEN; s++) {
            float4 v = e4[s * (B_SZ * E2D / 4) + col4];
            float a = sc[s];
            c0 = fmaf(a, v.x, c0);
            c1 = fmaf(a, v.y, c1);
            c2 = fmaf(a, v.z, c2);
            c3 = fmaf(a, v.w, c3);
        }
        float* dst = g_x + b * XDIM + tid * 4;
        dst[0] = c0; dst[1] = c1; dst[2] = c2; dst[3] = c3;
    }
}

// ---------------- GRU gate GEMMs: gi = W_ih@x + b_ih ; gh = W_hh@h + b_hh ---
// grid 384 blocks (192 gi + 192 gh), 256 threads; 8 output rows per block
__global__ void k_grugemm(const float* __restrict__ W_ih,
                          const float* __restrict__ b_ih,
                          const float* __restrict__ W_hh,
                          const float* __restrict__ b_hh) {
    __shared__ float xs[128 * 33];       // ~17 KB, transposed [k][b]
    int tid = threadIdx.x;
    bool is_gi = (blockIdx.x < 192);
    int o0 = (is_gi ? blockIdx.x : blockIdx.x - 192) * 8;
    const float* W    = is_gi ? W_ih : W_hh;
    const float* bias = is_gi ? b_ih : b_hh;
    const float* xsrc = is_gi ? g_x  : g_h;
    float* outp       = is_gi ? g_gi : g_gh;
    int K = is_gi ? XDIM : DHID;

    int b = tid & 31, oi = tid >> 5;
    int o = o0 + oi;
    float a0 = 0.f, a1 = 0.f, a2 = 0.f, a3 = 0.f;

    for (int kc = 0; kc < K; kc += 128) {
        __syncthreads();
        for (int i = tid; i < 128 * 32; i += 256) {
            int bb = i >> 7, kk = i & 127;
            xs[kk * 33 + bb] = xsrc[bb * K + kc + kk];
        }
        __syncthreads();
        const float* Wr = W + o * K + kc;
#pragma unroll 8
        for (int k = 0; k < 128; k += 4) {
            a0 = fmaf(Wr[k],     xs[k * 33 + b],       a0);
            a1 = fmaf(Wr[k + 1], xs[(k + 1) * 33 + b], a1);
            a2 = fmaf(Wr[k + 2], xs[(k + 2) * 33 + b], a2);
            a3 = fmaf(Wr[k + 3], xs[(k + 3) * 33 + b], a3);
        }
    }
    outp[o * B_SZ + b] = a0 + a1 + a2 + a3 + bias[o];
}

// ---------------- GRU elementwise: h_new ------------------------------------
// 64 blocks x 256 = 16384 threads
__global__ void k_gruelem() {
    int i = blockIdx.x * blockDim.x + threadIdx.x;   // i = d*32 + b
    if (i >= B_SZ * DHID) return;
    int b = i & 31, d = i >> 5;
    float gir = g_gi[d * B_SZ + b]            + g_gh[d * B_SZ + b];
    float giz = g_gi[(DHID + d) * B_SZ + b]   + g_gh[(DHID + d) * B_SZ + b];
    float gin = g_gi[(2 * DHID + d) * B_SZ + b];
    float ghn = g_gh[(2 * DHID + d) * B_SZ + b];
    float r = 1.f / (1.f + expf(-gir));
    float z = 1.f / (1.f + expf(-giz));
    float n = tanhf(fmaf(r, ghn, gin));
    float ho = g_h[b * DHID + d];
    g_h[b * DHID + d] = fmaf(z, ho - n, n);   // (1-z)*n + z*h
}

// ---------------- logits GEMM + fused argmax --------------------------------
// grid 250 blocks (128 vocab each), 128 threads; per-thread 4v x 8b
__global__ void k_logits(const float* __restrict__ Wo,
                         const float* __restrict__ bo,
                         float* __restrict__ out_t) {
    __shared__ float wo_s[32 * 129];     // [k][v], pad 129 -> conflict-free
    __shared__ float h_s[32 * 33];       // [k][b]
    __shared__ unsigned long long bmax[B_SZ];
    int tid = threadIdx.x;
    int tx = tid & 31;                   // v lane
    int ty = tid >> 5;                   // b group (0..3), 8 b each
    int v0 = blockIdx.x * 128;

    if (tid < B_SZ) bmax[tid] = 0ull;

    float acc0[8], acc1[8], acc2[8], acc3[8];
#pragma unroll
    for (int j = 0; j < 8; j++) { acc0[j] = acc1[j] = acc2[j] = acc3[j] = 0.f; }

    for (int kc = 0; kc < DHID; kc += 32) {
        __syncthreads();
        for (int i = tid; i < 128 * 32; i += 128) {        // Wo: coalesced k
            int v = i >> 5, k = i & 31;
            wo_s[k * 129 + v] = Wo[(v0 + v) * DHID + kc + k];
        }
        for (int i = tid; i < 32 * 32; i += 128) {         // h
            int b = i >> 5, k = i & 31;
            h_s[k * 33 + b] = g_h[b * DHID + kc + k];
        }
        __syncthreads();
#pragma unroll 4
        for (int k = 0; k < 32; k++) {
            const float* wr = &wo_s[k * 129 + tx];
            float w0 = wr[0], w1 = wr[32], w2 = wr[64], w3 = wr[96];
            const float* hr = &h_s[k * 33 + ty * 8];
#pragma unroll
            for (int bj = 0; bj < 8; bj++) {
                float hb = hr[bj];
                acc0[bj] = fmaf(w0, hb, acc0[bj]);
                acc1[bj] = fmaf(w1, hb, acc1[bj]);
                acc2[bj] = fmaf(w2, hb, acc2[bj]);
                acc3[bj] = fmaf(w3, hb, acc3[bj]);
            }
        }
    }

    int vb = v0 + tx;
    float bo0 = bo[vb], bo1 = bo[vb + 32], bo2 = bo[vb + 64], bo3 = bo[vb + 96];
#pragma unroll
    for (int bj = 0; bj < 8; bj++) {
        int b = ty * 8 + bj;
        float x0 = acc0[bj] + bo0;
        float x1 = acc1[bj] + bo1;
        float x2 = acc2[bj] + bo2;
        float x3 = acc3[bj] + bo3;
        float* orow = out_t + (size_t)b * VOCAB + vb;
        orow[0]  = x0;
        orow[32] = x1;
        orow[64] = x2;
        orow[96] = x3;
        float best = x0; int bi = vb;                       // strict > keeps lowest v
        if (x1 > best) { best = x1; bi = vb + 32; }
        if (x2 > best) { best = x2; bi = vb + 64; }
        if (x3 > best) { best = x3; bi = vb + 96; }
        atomicMax(&bmax[b], packkey(best, bi));
    }
    __syncthreads();
    if (tid < B_SZ) atomicMax(&g_amax[tid], bmax[tid]);
}

// ---------------- gather: x_emb = emb[argmax]; reset amax -------------------
// 32 blocks x 256
__global__ void k_gather(const float* __restrict__ emb) {
    int b = blockIdx.x;
    int tid = threadIdx.x;
    unsigned long long p = g_amax[b];
    int id = (int)(0x7FFFFFFFu - (unsigned int)(p & 0x7FFFFFFFull));
    g_x[b * XDIM + E2D + tid] = emb[(size_t)id * EMBD + tid];
    __syncthreads();
    if (tid == 0) g_amax[b] = 0ull;
}

// ---------------- launch ----------------------------------------------------
extern "C" void kernel_launch(void* const* d_in, const int* in_sizes, int n_in,
                              void* d_out, int out_size) {
    const float* enc   = (const float*)d_in[0];
    const int*   sos_p = (const int*)  d_in[2];
    const float* emb   = (const float*)d_in[3];
    const float* W1    = (const float*)d_in[4];
    const float* b1    = (const float*)d_in[5];
    const float* W2    = (const float*)d_in[6];
    const float* b2    = (const float*)d_in[7];
    const float* W_ih  = (const float*)d_in[8];
    const float* b_ih  = (const float*)d_in[9];
    const float* W_hh  = (const float*)d_in[10];
    const float* b_hh  = (const float*)d_in[11];
    const float* Wo    = (const float*)d_in[12];
    const float* bo    = (const float*)d_in[13];
    float* out = (float*)d_out;

    int T = out_size / (B_SZ * VOCAB);

    k_init<<<64, 256>>>(emb, sos_p);
    k_encproj<<<S_LEN * B_SZ / 8, 256>>>(enc, W1, b1);

    for (int t = 0; t < T; t++) {
        k_attn<<<B_SZ, 256>>>(enc, W1, W2, b2);
        k_grugemm<<<384, 256>>>(W_ih, b_ih, W_hh, b_hh);
        k_gruelem<<<64, 256>>>();
        k_logits<<<VOCAB / 128, 128>>>(Wo, bo, out + (size_t)t * B_SZ * VOCAB);
        k_gather<<<B_SZ, EMBD>>>(emb);
    }
}

// round 7
// speedup vs baseline: 1.3569x; 1.3569x over previous
#include <cuda_runtime.h>
#include <cstdint>

#define S_LEN  128
#define B_SZ   32
#define E2D    1024
#define DHID   512
#define AHID   32
#define EMBD   256
#define VOCAB  32000
#define CATD   1536   // DH + E2  (W1 row length)
#define XDIM   1280   // E2 + EMB (W_ih row length)
#define NSPI   10     // K-splits for gi (1280/128)
#define NSPH   4      // K-splits for gh (512/128)

// ---------------- device scratch (no allocation allowed) --------------------
__device__ __align__(16) float g_enc_proj[S_LEN * B_SZ * AHID]; // W1_enc@enc + b1
__device__ __align__(16) float g_h[B_SZ * DHID];                // hidden state
__device__ __align__(16) float g_ctx[B_SZ * E2D];               // attention context
__device__ __align__(16) float g_gip[NSPI * 3 * DHID * B_SZ];   // gi partials [sp][o][b]
__device__ __align__(16) float g_ghp[NSPH * 3 * DHID * B_SZ];   // gh partials [c][o][b]
__device__ unsigned long long g_amax[B_SZ];

// ---------------- helpers ---------------------------------------------------
__device__ __forceinline__ unsigned int fkey(float v) {
    unsigned int u = __float_as_uint(v);
    return (u & 0x80000000u) ? ~u : (u | 0x80000000u);
}
// larger value wins; on equal value LOWER index wins (jnp.argmax semantics)
__device__ __forceinline__ unsigned long long packkey(float v, int idx) {
    return ((unsigned long long)fkey(v) << 32) |
           (unsigned long long)(0x7FFFFFFFu - (unsigned int)idx);
}
__device__ __forceinline__ unsigned long long fdup(float x) {
    unsigned long long r;
    asm("mov.b64 %0, {%1, %1};" : "=l"(r) : "f"(x));
    return r;
}
__device__ __forceinline__ void ffma2(unsigned long long& d, unsigned long long a,
                                      unsigned long long b) {
    asm("fma.rn.f32x2 %0, %1, %2, %0;" : "+l"(d) : "l"(a), "l"(b));
}
__device__ __forceinline__ void funpk(float& lo, float& hi, unsigned long long v) {
    asm("mov.b64 {%0, %1}, %2;" : "=f"(lo), "=f"(hi) : "l"(v));
}

// ---------------- init: h=0, amax encodes sos token -------------------------
__global__ void k_init(const int* __restrict__ sos_p) {
    int i = blockIdx.x * blockDim.x + threadIdx.x;
    if (i < B_SZ * DHID) g_h[i] = 0.0f;
    if (i < B_SZ) {
        int sos = *sos_p;
        g_amax[i] = (unsigned long long)(0x7FFFFFFFu - (unsigned int)sos);
    }
}

// ---------------- one-time: enc_proj[sb][a] = W1[a,512:]@enc[sb] + b1[a] ----
__global__ void k_encproj(const float* __restrict__ enc,
                          const float* __restrict__ W1,
                          const float* __restrict__ b1) {
    __shared__ float enc_sh[8 * E2D];
    int tid = threadIdx.x;
    int sb0 = blockIdx.x * 8;
    for (int i = tid; i < 8 * E2D; i += 256)
        enc_sh[i] = enc[sb0 * E2D + i];
    __syncthreads();
    int a = tid & 31;
    int r = tid >> 5;
    const float* w = W1 + a * CATD + DHID;
    const float* e = enc_sh + r * E2D;
    float a0 = 0.f, a1 = 0.f, a2 = 0.f, a3 = 0.f;
#pragma unroll 8
    for (int k = 0; k < E2D; k += 4) {
        a0 = fmaf(w[k],     e[k],     a0);
        a1 = fmaf(w[k + 1], e[k + 1], a1);
        a2 = fmaf(w[k + 2], e[k + 2], a2);
        a3 = fmaf(w[k + 3], e[k + 3], a3);
    }
    g_enc_proj[(sb0 + r) * AHID + a] = a0 + a1 + a2 + a3 + b1[a];
}

// =============================================================================
// k_estep: one launch doing three independent jobs (all depend only on g_h):
//   blocks [0,48)   : gh partial GEMM for NEXT step   (W_hh @ h -> g_ghp)
//   blocks [48,80)  : attention + context for NEXT step (-> g_ctx)
//   blocks [80,330) : logits GEMM + fused argmax for THIS step (f32x2)
// =============================================================================
__global__ void __launch_bounds__(128) k_estep(
    const float* __restrict__ enc,
    const float* __restrict__ W1,
    const float* __restrict__ W2,
    const float* __restrict__ b2,
    const float* __restrict__ W_hh,
    const float* __restrict__ Wo,
    const float* __restrict__ bo,
    float* __restrict__ out_t) {
    __shared__ __align__(16) float sm[4128 + 1088];
    __shared__ unsigned long long bmax[B_SZ];
    int tid = threadIdx.x;
    int bk = blockIdx.x;

    if (bk < 48) {
        // ---- gh partial: tile 128o x 32b, K range [c*128, c*128+128) -------
        int c = bk & 3, ot = bk >> 2;
        int o0 = ot * 128, kc0 = c * 128;
        float* w_s = sm;              // [k][o] stride 129
        float* x_s = sm + 4128;       // [k][b] stride 33
        int tx = tid & 31, ty = tid >> 5;
        float acc[4][8] = {};
        for (int kc = kc0; kc < kc0 + 128; kc += 32) {
            __syncthreads();
            for (int i = tid; i < 128 * 32; i += 128) {
                int v = i >> 5, k = i & 31;
                w_s[k * 129 + v] = W_hh[(o0 + v) * DHID + kc + k];
            }
            for (int i = tid; i < 32 * 32; i += 128) {
                int b = i >> 5, k = i & 31;
                x_s[k * 33 + b] = g_h[b * DHID + kc + k];
            }
            __syncthreads();
#pragma unroll 4
            for (int k = 0; k < 32; k++) {
                const float* wr = &w_s[k * 129 + tx];
                float w0 = wr[0], w1 = wr[32], w2 = wr[64], w3 = wr[96];
                const float* hr = &x_s[k * 33 + ty * 8];
#pragma unroll
                for (int bj = 0; bj < 8; bj++) {
                    float hb = hr[bj];
                    acc[0][bj] = fmaf(w0, hb, acc[0][bj]);
                    acc[1][bj] = fmaf(w1, hb, acc[1][bj]);
                    acc[2][bj] = fmaf(w2, hb, acc[2][bj]);
                    acc[3][bj] = fmaf(w3, hb, acc[3][bj]);
                }
            }
        }
#pragma unroll
        for (int vi = 0; vi < 4; vi++)
#pragma unroll
            for (int bj = 0; bj < 8; bj++)
                g_ghp[(c * 3 * DHID + o0 + tx + vi * 32) * B_SZ + ty * 8 + bj] = acc[vi][bj];
        return;
    }

    if (bk < 80) {
        // ---- attention for next step, one block per batch ------------------
        int b = bk - 48;
        float* h_sh  = sm;         // 512
        float* part  = sm + 512;   // 4*32
        float* hproj = sm + 640;   // 32
        float* sc    = sm + 672;   // 128
        float* red   = sm + 800;   // 2
        for (int i = tid; i < DHID; i += 128) h_sh[i] = g_h[b * DHID + i];
        __syncthreads();
        {   // hproj[a] = W1[a,0:512] @ h : 4 segments of 128
            int a = tid & 31, seg = tid >> 5;
            const float* w  = W1 + a * CATD + seg * 128;
            const float* hh = h_sh + seg * 128;
            float acc = 0.f;
#pragma unroll 8
            for (int k = 0; k < 128; k++) acc = fmaf(w[k], hh[k], acc);
            part[seg * 32 + a] = acc;
        }
        __syncthreads();
        if (tid < AHID)
            hproj[tid] = part[tid] + part[32 + tid] + part[64 + tid] + part[96 + tid];
        __syncthreads();
        {   // scores over S (one thread per s)
            int s = tid;
            const float* ep = g_enc_proj + (s * B_SZ + b) * AHID;
            float sv = b2[0];
#pragma unroll
            for (int a = 0; a < AHID; a++) {
                float t = ep[a] + hproj[a];
                sv = fmaf(W2[a], fmaxf(t, 0.f), sv);
            }
            sc[s] = sv;
        }
        __syncthreads();
        if (tid < 32) {
            float m = fmaxf(fmaxf(sc[tid], sc[tid + 32]), fmaxf(sc[tid + 64], sc[tid + 96]));
#pragma unroll
            for (int off = 16; off > 0; off >>= 1)
                m = fmaxf(m, __shfl_xor_sync(0xffffffffu, m, off));
            if (tid == 0) red[0] = m;
        }
        __syncthreads();
        sc[tid] = expf(sc[tid] - red[0]);
        __syncthreads();
        if (tid < 32) {
            float s4 = sc[tid] + sc[tid + 32] + sc[tid + 64] + sc[tid + 96];
#pragma unroll
            for (int off = 16; off > 0; off >>= 1)
                s4 += __shfl_xor_sync(0xffffffffu, s4, off);
            if (tid == 0) red[1] = 1.0f / s4;
        }
        __syncthreads();
        sc[tid] *= red[1];
        __syncthreads();
        {   // context: each thread 8 consecutive e
            float acc[8] = {};
            const float4* e4 = reinterpret_cast<const float4*>(enc);
#pragma unroll 4
            for (int s = 0; s < S_LEN; s++) {
                float a = sc[s];
                int base4 = ((s * B_SZ + b) * E2D + tid * 8) >> 2;
                float4 v0 = e4[base4], v1 = e4[base4 + 1];
                acc[0] = fmaf(a, v0.x, acc[0]); acc[1] = fmaf(a, v0.y, acc[1]);
                acc[2] = fmaf(a, v0.z, acc[2]); acc[3] = fmaf(a, v0.w, acc[3]);
                acc[4] = fmaf(a, v1.x, acc[4]); acc[5] = fmaf(a, v1.y, acc[5]);
                acc[6] = fmaf(a, v1.z, acc[6]); acc[7] = fmaf(a, v1.w, acc[7]);
            }
            float* dst = g_ctx + b * E2D + tid * 8;
#pragma unroll
            for (int j = 0; j < 8; j++) dst[j] = acc[j];
        }
        return;
    }

    // ---- logits (f32x2) + fused argmax -------------------------------------
    if (out_t == nullptr) return;
    float* wo_s = sm;              // [k][v] stride 129 (4128 floats)
    float* h_s  = sm + 4128;       // [k][b] stride 34 (8B-aligned pairs)
    int tx = tid & 31, ty = tid >> 5;
    int v0 = (bk - 80) * 128;
    if (tid < B_SZ) bmax[tid] = 0ull;

    unsigned long long acc[4][4];  // [v][b-pair], each = 2 packed f32 accums
#pragma unroll
    for (int i = 0; i < 4; i++)
#pragma unroll
        for (int j = 0; j < 4; j++) acc[i][j] = 0ull;

    for (int kc = 0; kc < DHID; kc += 32) {
        __syncthreads();
        for (int i = tid; i < 128 * 32; i += 128) {
            int v = i >> 5, k = i & 31;
            wo_s[k * 129 + v] = Wo[(v0 + v) * DHID + kc + k];
        }
        for (int i = tid; i < 32 * 32; i += 128) {
            int b = i >> 5, k = i & 31;
            h_s[k * 34 + b] = g_h[b * DHID + kc + k];
        }
        __syncthreads();
#pragma unroll 2
        for (int k = 0; k < 32; k++) {
            const float* wr = &wo_s[k * 129 + tx];
            unsigned long long W0 = fdup(wr[0]);
            unsigned long long W1d = fdup(wr[32]);
            unsigned long long W2d = fdup(wr[64]);
            unsigned long long W3 = fdup(wr[96]);
            const unsigned long long* hp =
                reinterpret_cast<const unsigned long long*>(h_s + k * 34 + ty * 8);
            unsigned long long H0 = hp[0], H1 = hp[1], H2 = hp[2], H3 = hp[3];
            ffma2(acc[0][0], W0, H0); ffma2(acc[0][1], W0, H1);
            ffma2(acc[0][2], W0, H2); ffma2(acc[0][3], W0, H3);
            ffma2(acc[1][0], W1d, H0); ffma2(acc[1][1], W1d, H1);
            ffma2(acc[1][2], W1d, H2); ffma2(acc[1][3], W1d, H3);
            ffma2(acc[2][0], W2d, H0); ffma2(acc[2][1], W2d, H1);
            ffma2(acc[2][2], W2d, H2); ffma2(acc[2][3], W2d, H3);
            ffma2(acc[3][0], W3, H0); ffma2(acc[3][1], W3, H1);
            ffma2(acc[3][2], W3, H2); ffma2(acc[3][3], W3, H3);
        }
    }

    int vb = v0 + tx;
    float bb0 = bo[vb], bb1 = bo[vb + 32], bb2 = bo[vb + 64], bb3 = bo[vb + 96];
#pragma unroll
    for (int p = 0; p < 4; p++) {
        int b0 = ty * 8 + 2 * p, b1 = b0 + 1;
        float x00, x01, x10, x11, x20, x21, x30, x31;
        funpk(x00, x01, acc[0][p]); funpk(x10, x11, acc[1][p]);
        funpk(x20, x21, acc[2][p]); funpk(x30, x31, acc[3][p]);
        x00 += bb0; x10 += bb1; x20 += bb2; x30 += bb3;
        x01 += bb0; x11 += bb1; x21 += bb2; x31 += bb3;
        float* o0 = out_t + (size_t)b0 * VOCAB + vb;
        float* o1 = out_t + (size_t)b1 * VOCAB + vb;
        o0[0] = x00; o0[32] = x10; o0[64] = x20; o0[96] = x30;
        o1[0] = x01; o1[32] = x11; o1[64] = x21; o1[96] = x31;
        float be0 = x00; int bi0 = vb;
        if (x10 > be0) { be0 = x10; bi0 = vb + 32; }
        if (x20 > be0) { be0 = x20; bi0 = vb + 64; }
        if (x30 > be0) { be0 = x30; bi0 = vb + 96; }
        float be1 = x01; int bi1 = vb;
        if (x11 > be1) { be1 = x11; bi1 = vb + 32; }
        if (x21 > be1) { be1 = x21; bi1 = vb + 64; }
        if (x31 > be1) { be1 = x31; bi1 = vb + 96; }
        atomicMax(&bmax[b0], packkey(be0, bi0));
        atomicMax(&bmax[b1], packkey(be1, bi1));
    }
    __syncthreads();
    if (tid < B_SZ) atomicMax(&g_amax[tid], bmax[tid]);
}

// ---------------- gi partial GEMM (x = [ctx | emb[argmax]]) -----------------
// grid 120 blocks (12 o-tiles x 10 K-splits), 128 threads
__global__ void __launch_bounds__(128) k_gigemm(const float* __restrict__ W_ih,
                                                const float* __restrict__ emb) {
    __shared__ __align__(16) float w_s[32 * 129];
    __shared__ float x_s[32 * 33];
    __shared__ int sh_id[B_SZ];
    int tid = threadIdx.x;
    int ot = blockIdx.x % 12, sp = blockIdx.x / 12;
    int o0 = ot * 128, kc0 = sp * 128;
    if (tid < B_SZ) {
        unsigned long long p = g_amax[tid];
        sh_id[tid] = (int)(0x7FFFFFFFu - (unsigned int)(p & 0x7FFFFFFFull));
    }
    int tx = tid & 31, ty = tid >> 5;
    float acc[4][8] = {};
    for (int kc = kc0; kc < kc0 + 128; kc += 32) {
        __syncthreads();
        for (int i = tid; i < 128 * 32; i += 128) {
            int v = i >> 5, k = i & 31;
            w_s[k * 129 + v] = W_ih[(o0 + v) * XDIM + kc + k];
        }
        for (int i = tid; i < 32 * 32; i += 128) {
            int b = i >> 5, k = i & 31;
            int kg = kc + k;
            float val = (kc0 < E2D) ? g_ctx[b * E2D + kg]
                                    : emb[(size_t)sh_id[b] * EMBD + (kg - E2D)];
            x_s[k * 33 + b] = val;
        }
        __syncthreads();
#pragma unroll 4
        for (int k = 0; k < 32; k++) {
            const float* wr = &w_s[k * 129 + tx];
            float w0 = wr[0], w1 = wr[32], w2 = wr[64], w3 = wr[96];
            const float* hr = &x_s[k * 33 + ty * 8];
#pragma unroll
            for (int bj = 0; bj < 8; bj++) {
                float hb = hr[bj];
                acc[0][bj] = fmaf(w0, hb, acc[0][bj]);
                acc[1][bj] = fmaf(w1, hb, acc[1][bj]);
                acc[2][bj] = fmaf(w2, hb, acc[2][bj]);
                acc[3][bj] = fmaf(w3, hb, acc[3][bj]);
            }
        }
    }
#pragma unroll
    for (int vi = 0; vi < 4; vi++)
#pragma unroll
        for (int bj = 0; bj < 8; bj++)
            g_gip[(sp * 3 * DHID + o0 + tx + vi * 32) * B_SZ + ty * 8 + bj] = acc[vi][bj];
}

// ---------------- GRU elementwise: sum partials, gates, h_new ---------------
__global__ void k_gruelem(const float* __restrict__ b_ih,
                          const float* __restrict__ b_hh) {
    int i = blockIdx.x * blockDim.x + threadIdx.x;
    if (i >= B_SZ * DHID) return;
    int b = i & 31, d = i >> 5;
    float gr = 0.f, gz = 0.f, gn = 0.f;
#pragma unroll
    for (int sp = 0; sp < NSPI; sp++) {
        int base = (sp * 3 * DHID + d) * B_SZ + b;
        gr += g_gip[base];
        gz += g_gip[base + DHID * B_SZ];
        gn += g_gip[base + 2 * DHID * B_SZ];
    }
    float hr = 0.f, hz = 0.f, hn = 0.f;
#pragma unroll
    for (int c = 0; c < NSPH; c++) {
        int base = (c * 3 * DHID + d) * B_SZ + b;
        hr += g_ghp[base];
        hz += g_ghp[base + DHID * B_SZ];
        hn += g_ghp[base + 2 * DHID * B_SZ];
    }
    float gir = gr + hr + b_ih[d] + b_hh[d];
    float giz = gz + hz + b_ih[DHID + d] + b_hh[DHID + d];
    float gin = gn + b_ih[2 * DHID + d];
    float ghn = hn + b_hh[2 * DHID + d];
    float r = 1.f / (1.f + expf(-gir));
    float z = 1.f / (1.f + expf(-giz));
    float n = tanhf(fmaf(r, ghn, gin));
    float ho = g_h[b * DHID + d];
    g_h[b * DHID + d] = fmaf(z, ho - n, n);
    if (i < B_SZ) g_amax[i] = 0ull;   // reset before this step's logits atomics
}

// ---------------- launch ----------------------------------------------------
extern "C" void kernel_launch(void* const* d_in, const int* in_sizes, int n_in,
                              void* d_out, int out_size) {
    const float* enc   = (const float*)d_in[0];
    const int*   sos_p = (const int*)  d_in[2];
    const float* emb   = (const float*)d_in[3];
    const float* W1    = (const float*)d_in[4];
    const float* b1    = (const float*)d_in[5];
    const float* W2    = (const float*)d_in[6];
    const float* b2    = (const float*)d_in[7];
    const float* W_ih  = (const float*)d_in[8];
    const float* b_ih  = (const float*)d_in[9];
    const float* W_hh  = (const float*)d_in[10];
    const float* b_hh  = (const float*)d_in[11];
    const float* Wo    = (const float*)d_in[12];
    const float* bo    = (const float*)d_in[13];
    float* out = (float*)d_out;

    int T = out_size / (B_SZ * VOCAB);

    k_init<<<64, 256>>>(sos_p);
    k_encproj<<<S_LEN * B_SZ / 8, 256>>>(enc, W1, b1);
    // prologue: attn(0) + gh(0), no logits
    k_estep<<<330, 128>>>(enc, W1, W2, b2, W_hh, Wo, bo, nullptr);

    for (int t = 0; t < T; t++) {
        k_gigemm<<<120, 128>>>(W_ih, emb);
        k_gruelem<<<64, 256>>>(b_ih, b_hh);
        // logits(t) + attn(t+1) + gh(t+1)  (the t=T-1 extras are harmless)
        k_estep<<<330, 128>>>(enc, W1, W2, b2, W_hh, Wo, bo,
                              out + (size_t)t * B_SZ * VOCAB);
    }
}

// round 9
// speedup vs baseline: 2.8850x; 2.1262x over previous
#include <cuda_runtime.h>
#include <cstdint>

#define S_LEN  128
#define B_SZ   32
#define E2D    1024
#define DHID   512
#define AHID   32
#define EMBD   256
#define VOCAB  32000
#define CATD   1536   // DH + E2  (W1 row length)
#define XDIM   1280   // E2 + EMB (W_ih row length)
#define NSPI   10     // K-splits for gi (1280/128)
#define NSPH   4      // K-splits for gh (512/128)

// ---------------- device scratch (no allocation allowed) --------------------
__device__ __align__(16) float g_enc_proj[S_LEN * B_SZ * AHID]; // W1_enc@enc + b1
__device__ __align__(16) float g_h[B_SZ * DHID];                // hidden state
__device__ __align__(16) float g_ctx[B_SZ * E2D];               // attention context
__device__ __align__(16) float g_gip[NSPI * 3 * DHID * B_SZ];   // gi partials [sp][o][b]
__device__ __align__(16) float g_ghp[NSPH * 3 * DHID * B_SZ];   // gh partials [c][o][b]
__device__ unsigned long long g_amax[B_SZ];

// ---------------- helpers ---------------------------------------------------
__device__ __forceinline__ unsigned int fkey(float v) {
    unsigned int u = __float_as_uint(v);
    return (u & 0x80000000u) ? ~u : (u | 0x80000000u);
}
// larger value wins; on equal value LOWER index wins (jnp.argmax semantics)
__device__ __forceinline__ unsigned long long packkey(float v, int idx) {
    return ((unsigned long long)fkey(v) << 32) |
           (unsigned long long)(0x7FFFFFFFu - (unsigned int)idx);
}
__device__ __forceinline__ unsigned long long fdup(float x) {
    unsigned long long r;
    asm("mov.b64 %0, {%1, %1};" : "=l"(r) : "f"(x));
    return r;
}
__device__ __forceinline__ void ffma2(unsigned long long& d, unsigned long long a,
                                      unsigned long long b) {
    asm("fma.rn.f32x2 %0, %1, %2, %0;" : "+l"(d) : "l"(a), "l"(b));
}
__device__ __forceinline__ void funpk(float& lo, float& hi, unsigned long long v) {
    asm("mov.b64 {%0, %1}, %2;" : "=f"(lo), "=f"(hi) : "l"(v));
}

// ---------------- init: h=0, amax encodes sos token -------------------------
__global__ void k_init(const int* __restrict__ sos_p) {
    int i = blockIdx.x * blockDim.x + threadIdx.x;
    if (i < B_SZ * DHID) g_h[i] = 0.0f;
    if (i < B_SZ) {
        int sos = *sos_p;
        g_amax[i] = (unsigned long long)(0x7FFFFFFFu - (unsigned int)sos);
    }
}

// ---------------- one-time: enc_proj[sb][a] = W1[a,512:]@enc[sb] + b1[a] ----
__global__ void k_encproj(const float* __restrict__ enc,
                          const float* __restrict__ W1,
                          const float* __restrict__ b1) {
    __shared__ float enc_sh[8 * E2D];
    int tid = threadIdx.x;
    int sb0 = blockIdx.x * 8;
    for (int i = tid; i < 8 * E2D; i += 256)
        enc_sh[i] = enc[sb0 * E2D + i];
    __syncthreads();
    int a = tid & 31;
    int r = tid >> 5;
    const float* w = W1 + a * CATD + DHID;
    const float* e = enc_sh + r * E2D;
    float a0 = 0.f, a1 = 0.f, a2 = 0.f, a3 = 0.f;
#pragma unroll 8
    for (int k = 0; k < E2D; k += 4) {
        a0 = fmaf(w[k],     e[k],     a0);
        a1 = fmaf(w[k + 1], e[k + 1], a1);
        a2 = fmaf(w[k + 2], e[k + 2], a2);
        a3 = fmaf(w[k + 3], e[k + 3], a3);
    }
    g_enc_proj[(sb0 + r) * AHID + a] = a0 + a1 + a2 + a3 + b1[a];
}

// =============================================================================
// k_estep: one launch doing three independent jobs (all depend only on g_h):
//   blocks [0,250)   : logits GEMM + fused argmax for THIS step (f32x2)
//   blocks [250,298) : gh partial GEMM for NEXT step   (W_hh @ h -> g_ghp)
//   blocks [298,330) : attention + context for NEXT step (-> g_ctx)
// Register-prefetch pipeline hides L2 latency behind FMA in both GEMM roles.
// =============================================================================
__global__ void __launch_bounds__(128) k_estep(
    const float* __restrict__ enc,
    const float* __restrict__ W1,
    const float* __restrict__ W2,
    const float* __restrict__ b2,
    const float* __restrict__ W_hh,
    const float* __restrict__ Wo,
    const float* __restrict__ bo,
    float* __restrict__ out_t) {
    __shared__ __align__(16) float sm[4128 + 1088];
    __shared__ unsigned long long bmax[B_SZ];
    int tid = threadIdx.x;
    int bk = blockIdx.x;
    int tk = tid & 31;          // k-lane during staging
    int tg = tid >> 5;          // group during staging

    if (bk < 250) {
        // ---- logits (f32x2) + fused argmax ---------------------------------
        if (out_t == nullptr) return;
        float* wo_s = sm;              // [k][v] stride 129
        float* h_s  = sm + 4128;       // [k][b] stride 34 (8B-aligned pairs)
        int tx = tid & 31, ty = tid >> 5;
        int v0 = bk * 128;
        if (tid < B_SZ) bmax[tid] = 0ull;

        unsigned long long acc[4][4];  // [v][b-pair]
#pragma unroll
        for (int i = 0; i < 4; i++)
#pragma unroll
            for (int j = 0; j < 4; j++) acc[i][j] = 0ull;

        float pw[32], ph[8];
        // prefetch chunk kc=0: thread covers k=tk fixed, v=tg+4j / b=tg+4j
#pragma unroll
        for (int j = 0; j < 32; j++)
            pw[j] = Wo[(size_t)(v0 + tg + 4 * j) * DHID + tk];
#pragma unroll
        for (int j = 0; j < 8; j++)
            ph[j] = g_h[(tg + 4 * j) * DHID + tk];

        for (int kc = 0; kc < DHID; kc += 32) {
            __syncthreads();
#pragma unroll
            for (int j = 0; j < 32; j++) wo_s[tk * 129 + tg + 4 * j] = pw[j];
#pragma unroll
            for (int j = 0; j < 8; j++)  h_s[tk * 34 + tg + 4 * j] = ph[j];
            __syncthreads();
            if (kc + 32 < DHID) {
#pragma unroll
                for (int j = 0; j < 32; j++)
                    pw[j] = Wo[(size_t)(v0 + tg + 4 * j) * DHID + kc + 32 + tk];
#pragma unroll
                for (int j = 0; j < 8; j++)
                    ph[j] = g_h[(tg + 4 * j) * DHID + kc + 32 + tk];
            }
#pragma unroll 2
            for (int k = 0; k < 32; k++) {
                const float* wr = &wo_s[k * 129 + tx];
                unsigned long long W0 = fdup(wr[0]);
                unsigned long long W1d = fdup(wr[32]);
                unsigned long long W2d = fdup(wr[64]);
                unsigned long long W3 = fdup(wr[96]);
                const unsigned long long* hp =
                    reinterpret_cast<const unsigned long long*>(h_s + k * 34 + ty * 8);
                unsigned long long H0 = hp[0], H1 = hp[1], H2 = hp[2], H3 = hp[3];
                ffma2(acc[0][0], W0, H0); ffma2(acc[0][1], W0, H1);
                ffma2(acc[0][2], W0, H2); ffma2(acc[0][3], W0, H3);
                ffma2(acc[1][0], W1d, H0); ffma2(acc[1][1], W1d, H1);
                ffma2(acc[1][2], W1d, H2); ffma2(acc[1][3], W1d, H3);
                ffma2(acc[2][0], W2d, H0); ffma2(acc[2][1], W2d, H1);
                ffma2(acc[2][2], W2d, H2); ffma2(acc[2][3], W2d, H3);
                ffma2(acc[3][0], W3, H0); ffma2(acc[3][1], W3, H1);
                ffma2(acc[3][2], W3, H2); ffma2(acc[3][3], W3, H3);
            }
        }

        int vb = v0 + tx;
        float bb0 = bo[vb], bb1 = bo[vb + 32], bb2 = bo[vb + 64], bb3 = bo[vb + 96];
#pragma unroll
        for (int p = 0; p < 4; p++) {
            int b0 = ty * 8 + 2 * p, b1 = b0 + 1;
            float x00, x01, x10, x11, x20, x21, x30, x31;
            funpk(x00, x01, acc[0][p]); funpk(x10, x11, acc[1][p]);
            funpk(x20, x21, acc[2][p]); funpk(x30, x31, acc[3][p]);
            x00 += bb0; x10 += bb1; x20 += bb2; x30 += bb3;
            x01 += bb0; x11 += bb1; x21 += bb2; x31 += bb3;
            float* o0 = out_t + (size_t)b0 * VOCAB + vb;
            float* o1 = out_t + (size_t)b1 * VOCAB + vb;
            // evict-first stores: keep weights resident in L2 across steps
            __stcs(o0,      x00); __stcs(o0 + 32, x10);
            __stcs(o0 + 64, x20); __stcs(o0 + 96, x30);
            __stcs(o1,      x01); __stcs(o1 + 32, x11);
            __stcs(o1 + 64, x21); __stcs(o1 + 96, x31);
            float be0 = x00; int bi0 = vb;
            if (x10 > be0) { be0 = x10; bi0 = vb + 32; }
            if (x20 > be0) { be0 = x20; bi0 = vb + 64; }
            if (x30 > be0) { be0 = x30; bi0 = vb + 96; }
            float be1 = x01; int bi1 = vb;
            if (x11 > be1) { be1 = x11; bi1 = vb + 32; }
            if (x21 > be1) { be1 = x21; bi1 = vb + 64; }
            if (x31 > be1) { be1 = x31; bi1 = vb + 96; }
            atomicMax(&bmax[b0], packkey(be0, bi0));
            atomicMax(&bmax[b1], packkey(be1, bi1));
        }
        __syncthreads();
        if (tid < B_SZ) atomicMax(&g_amax[tid], bmax[tid]);
        return;
    }

    if (bk < 298) {
        // ---- gh partial: tile 128o x 32b, K range [c*128, c*128+128) -------
        int r = bk - 250;
        int c = r & 3, ot = r >> 2;
        int o0 = ot * 128, kc0 = c * 128;
        float* w_s = sm;              // [k][o] stride 129
        float* x_s = sm + 4128;       // [k][b] stride 33
        int tx = tid & 31, ty = tid >> 5;
        float acc[4][8] = {};
        float pw[32], ph[8];
#pragma unroll
        for (int j = 0; j < 32; j++)
            pw[j] = W_hh[(o0 + tg + 4 * j) * DHID + kc0 + tk];
#pragma unroll
        for (int j = 0; j < 8; j++)
            ph[j] = g_h[(tg + 4 * j) * DHID + kc0 + tk];
        for (int kc = kc0; kc < kc0 + 128; kc += 32) {
            __syncthreads();
#pragma unroll
            for (int j = 0; j < 32; j++) w_s[tk * 129 + tg + 4 * j] = pw[j];
#pragma unroll
            for (int j = 0; j < 8; j++)  x_s[tk * 33 + tg + 4 * j] = ph[j];
            __syncthreads();
            if (kc + 32 < kc0 + 128) {
#pragma unroll
                for (int j = 0; j < 32; j++)
                    pw[j] = W_hh[(o0 + tg + 4 * j) * DHID + kc + 32 + tk];
#pragma unroll
                for (int j = 0; j < 8; j++)
                    ph[j] = g_h[(tg + 4 * j) * DHID + kc + 32 + tk];
            }
#pragma unroll 4
            for (int k = 0; k < 32; k++) {
                const float* wr = &w_s[k * 129 + tx];
                float w0 = wr[0], w1 = wr[32], w2 = wr[64], w3 = wr[96];
                const float* hr = &x_s[k * 33 + ty * 8];
#pragma unroll
                for (int bj = 0; bj < 8; bj++) {
                    float hb = hr[bj];
                    acc[0][bj] = fmaf(w0, hb, acc[0][bj]);
                    acc[1][bj] = fmaf(w1, hb, acc[1][bj]);
                    acc[2][bj] = fmaf(w2, hb, acc[2][bj]);
                    acc[3][bj] = fmaf(w3, hb, acc[3][bj]);
                }
            }
        }
#pragma unroll
        for (int vi = 0; vi < 4; vi++)
#pragma unroll
            for (int bj = 0; bj < 8; bj++)
                g_ghp[(c * 3 * DHID + o0 + tx + vi * 32) * B_SZ + ty * 8 + bj] = acc[vi][bj];
        return;
    }

    // ---- attention for next step, one block per batch ----------------------
    {
        int b = bk - 298;
        float* h_sh  = sm;         // 512
        float* part  = sm + 512;   // 4*32
        float* hproj = sm + 640;   // 32
        float* sc    = sm + 672;   // 128
        float* red   = sm + 800;   // 2
        for (int i = tid; i < DHID; i += 128) h_sh[i] = g_h[b * DHID + i];
        __syncthreads();
        {   // hproj[a] = W1[a,0:512] @ h : 4 segments of 128
            int a = tid & 31, seg = tid >> 5;
            const float* w  = W1 + a * CATD + seg * 128;
            const float* hh = h_sh + seg * 128;
            float acc = 0.f;
#pragma unroll 8
            for (int k = 0; k < 128; k++) acc = fmaf(w[k], hh[k], acc);
            part[seg * 32 + a] = acc;
        }
        __syncthreads();
        if (tid < AHID)
            hproj[tid] = part[tid] + part[32 + tid] + part[64 + tid] + part[96 + tid];
        __syncthreads();
        {   // scores over S (one thread per s)
            int s = tid;
            const float* ep = g_enc_proj + (s * B_SZ + b) * AHID;
            float sv = b2[0];
#pragma unroll
            for (int a = 0; a < AHID; a++) {
                float t = ep[a] + hproj[a];
                sv = fmaf(W2[a], fmaxf(t, 0.f), sv);
            }
            sc[s] = sv;
        }
        __syncthreads();
        if (tid < 32) {
            float m = fmaxf(fmaxf(sc[tid], sc[tid + 32]), fmaxf(sc[tid + 64], sc[tid + 96]));
#pragma unroll
            for (int off = 16; off > 0; off >>= 1)
                m = fmaxf(m, __shfl_xor_sync(0xffffffffu, m, off));
            if (tid == 0) red[0] = m;
        }
        __syncthreads();
        sc[tid] = expf(sc[tid] - red[0]);
        __syncthreads();
        if (tid < 32) {
            float s4 = sc[tid] + sc[tid + 32] + sc[tid + 64] + sc[tid + 96];
#pragma unroll
            for (int off = 16; off > 0; off >>= 1)
                s4 += __shfl_xor_sync(0xffffffffu, s4, off);
            if (tid == 0) red[1] = 1.0f / s4;
        }
        __syncthreads();
        sc[tid] *= red[1];
        __syncthreads();
        {   // context: each thread 8 consecutive e
            float acc[8] = {};
            const float4* e4 = reinterpret_cast<const float4*>(enc);
#pragma unroll 4
            for (int s = 0; s < S_LEN; s++) {
                float a = sc[s];
                int base4 = ((s * B_SZ + b) * E2D + tid * 8) >> 2;
                float4 v0 = e4[base4], v1 = e4[base4 + 1];
                acc[0] = fmaf(a, v0.x, acc[0]); acc[1] = fmaf(a, v0.y, acc[1]);
                acc[2] = fmaf(a, v0.z, acc[2]); acc[3] = fmaf(a, v0.w, acc[3]);
                acc[4] = fmaf(a, v1.x, acc[4]); acc[5] = fmaf(a, v1.y, acc[5]);
                acc[6] = fmaf(a, v1.z, acc[6]); acc[7] = fmaf(a, v1.w, acc[7]);
            }
            float* dst = g_ctx + b * E2D + tid * 8;
#pragma unroll
            for (int j = 0; j < 8; j++) dst[j] = acc[j];
        }
    }
}

// ---------------- gi partial GEMM (x = [ctx | emb[argmax]]) -----------------
// grid 120 blocks (12 o-tiles x 10 K-splits), 128 threads
__global__ void __launch_bounds__(128) k_gigemm(const float* __restrict__ W_ih,
                                                const float* __restrict__ emb) {
    __shared__ __align__(16) float w_s[32 * 129];
    __shared__ float x_s[32 * 33];
    __shared__ int sh_id[B_SZ];
    int tid = threadIdx.x;
    int ot = blockIdx.x % 12, sp = blockIdx.x / 12;
    int o0 = ot * 128, kc0 = sp * 128;
    int tk = tid & 31, tg = tid >> 5;
    if (tid < B_SZ) {
        unsigned long long p = g_amax[tid];
        sh_id[tid] = (int)(0x7FFFFFFFu - (unsigned int)(p & 0x7FFFFFFFull));
    }
    __syncthreads();
    int tx = tid & 31, ty = tid >> 5;
    bool is_ctx = (kc0 < E2D);
    float acc[4][8] = {};
    float pw[32], px[8];
#pragma unroll
    for (int j = 0; j < 32; j++)
        pw[j] = W_ih[(o0 + tg + 4 * j) * XDIM + kc0 + tk];
#pragma unroll
    for (int j = 0; j < 8; j++) {
        int b = tg + 4 * j, kg = kc0 + tk;
        px[j] = is_ctx ? g_ctx[b * E2D + kg]
                       : emb[(size_t)sh_id[b] * EMBD + (kg - E2D)];
    }
    for (int kc = kc0; kc < kc0 + 128; kc += 32) {
        __syncthreads();
#pragma unroll
        for (int j = 0; j < 32; j++) w_s[tk * 129 + tg + 4 * j] = pw[j];
#pragma unroll
        for (int j = 0; j < 8; j++)  x_s[tk * 33 + tg + 4 * j] = px[j];
        __syncthreads();
        if (kc + 32 < kc0 + 128) {
#pragma unroll
            for (int j = 0; j < 32; j++)
                pw[j] = W_ih[(o0 + tg + 4 * j) * XDIM + kc + 32 + tk];
#pragma unroll
            for (int j = 0; j < 8; j++) {
                int b = tg + 4 * j, kg = kc + 32 + tk;
                px[j] = is_ctx ? g_ctx[b * E2D + kg]
                               : emb[(size_t)sh_id[b] * EMBD + (kg - E2D)];
            }
        }
#pragma unroll 4
        for (int k = 0; k < 32; k++) {
            const float* wr = &w_s[k * 129 + tx];
            float w0 = wr[0], w1 = wr[32], w2 = wr[64], w3 = wr[96];
            const float* hr = &x_s[k * 33 + ty * 8];
#pragma unroll
            for (int bj = 0; bj < 8; bj++) {
                float hb = hr[bj];
                acc[0][bj] = fmaf(w0, hb, acc[0][bj]);
                acc[1][bj] = fmaf(w1, hb, acc[1][bj]);
                acc[2][bj] = fmaf(w2, hb, acc[2][bj]);
                acc[3][bj] = fmaf(w3, hb, acc[3][bj]);
            }
        }
    }
#pragma unroll
    for (int vi = 0; vi < 4; vi++)
#pragma unroll
        for (int bj = 0; bj < 8; bj++)
            g_gip[(sp * 3 * DHID + o0 + tx + vi * 32) * B_SZ + ty * 8 + bj] = acc[vi][bj];
}

// ---------------- GRU elementwise: sum partials, gates, h_new ---------------
__global__ void __launch_bounds__(128) k_gruelem(const float* __restrict__ b_ih,
                                                 const float* __restrict__ b_hh) {
    int i = blockIdx.x * blockDim.x + threadIdx.x;
    if (i >= B_SZ * DHID) return;
    int b = i & 31, d = i >> 5;
    float gr = 0.f, gz = 0.f, gn = 0.f;
#pragma unroll
    for (int sp = 0; sp < NSPI; sp++) {
        int base = (sp * 3 * DHID + d) * B_SZ + b;
        gr += g_gip[base];
        gz += g_gip[base + DHID * B_SZ];
        gn += g_gip[base + 2 * DHID * B_SZ];
    }
    float hr = 0.f, hz = 0.f, hn = 0.f;
#pragma unroll
    for (int c = 0; c < NSPH; c++) {
        int base = (c * 3 * DHID + d) * B_SZ + b;
        hr += g_ghp[base];
        hz += g_ghp[base + DHID * B_SZ];
        hn += g_ghp[base + 2 * DHID * B_SZ];
    }
    float gir = gr + hr + b_ih[d] + b_hh[d];
    float giz = gz + hz + b_ih[DHID + d] + b_hh[DHID + d];
    float gin = gn + b_ih[2 * DHID + d];
    float ghn = hn + b_hh[2 * DHID + d];
    float r = 1.f / (1.f + expf(-gir));
    float z = 1.f / (1.f + expf(-giz));
    float n = tanhf(fmaf(r, ghn, gin));
    float ho = g_h[b * DHID + d];
    g_h[b * DHID + d] = fmaf(z, ho - n, n);
    if (i < B_SZ) g_amax[i] = 0ull;   // reset before this step's logits atomics
}

// ---------------- launch ----------------------------------------------------
extern "C" void kernel_launch(void* const* d_in, const int* in_sizes, int n_in,
                              void* d_out, int out_size) {
    const float* enc   = (const float*)d_in[0];
    const int*   sos_p = (const int*)  d_in[2];
    const float* emb   = (const float*)d_in[3];
    const float* W1    = (const float*)d_in[4];
    const float* b1    = (const float*)d_in[5];
    const float* W2    = (const float*)d_in[6];
    const float* b2    = (const float*)d_in[7];
    const float* W_ih  = (const float*)d_in[8];
    const float* b_ih  = (const float*)d_in[9];
    const float* W_hh  = (const float*)d_in[10];
    const float* b_hh  = (const float*)d_in[11];
    const float* Wo    = (const float*)d_in[12];
    const float* bo    = (const float*)d_in[13];
    float* out = (float*)d_out;

    int T = out_size / (B_SZ * VOCAB);

    k_init<<<64, 256>>>(sos_p);
    k_encproj<<<S_LEN * B_SZ / 8, 256>>>(enc, W1, b1);
    // prologue: attn(0) + gh(0), no logits
    k_estep<<<330, 128>>>(enc, W1, W2, b2, W_hh, Wo, bo, nullptr);

    for (int t = 0; t < T; t++) {
        k_gigemm<<<120, 128>>>(W_ih, emb);
        k_gruelem<<<128, 128>>>(b_ih, b_hh);
        // logits(t) + attn(t+1) + gh(t+1)  (the t=T-1 extras are harmless)
        k_estep<<<330, 128>>>(enc, W1, W2, b2, W_hh, Wo, bo,
                              out + (size_t)t * B_SZ * VOCAB);
    }
}

// round 10
// speedup vs baseline: 2.9647x; 1.0276x over previous
#include <cuda_runtime.h>
#include <cstdint>

#define S_LEN  128
#define B_SZ   32
#define E2D    1024
#define DHID   512
#define AHID   32
#define EMBD   256
#define VOCAB  32000
#define CATD   1536   // DH + E2  (W1 row length)
#define XDIM   1280   // E2 + EMB (W_ih row length)
#define NSPI   10     // K-splits for gi (1280/128)
#define NSPH   4      // K-splits for gh (512/128)

// ---------------- device scratch (no allocation allowed) --------------------
__device__ __align__(16) float g_enc_proj[S_LEN * B_SZ * AHID]; // W1_enc@enc + b1
__device__ __align__(16) float g_h[B_SZ * DHID];                // hidden state
__device__ __align__(16) float g_ctx[B_SZ * E2D];               // attention context
__device__ __align__(16) float g_gip[NSPI * 3 * DHID * B_SZ];   // gi partials [sp][o][b]
__device__ __align__(16) float g_ghp[NSPH * 3 * DHID * B_SZ];   // gh partials [c][o][b]
__device__ unsigned long long g_amax[B_SZ];

// ---------------- helpers ---------------------------------------------------
__device__ __forceinline__ unsigned int fkey(float v) {
    unsigned int u = __float_as_uint(v);
    return (u & 0x80000000u) ? ~u : (u | 0x80000000u);
}
// larger value wins; on equal value LOWER index wins (jnp.argmax semantics)
__device__ __forceinline__ unsigned long long packkey(float v, int idx) {
    return ((unsigned long long)fkey(v) << 32) |
           (unsigned long long)(0x7FFFFFFFu - (unsigned int)idx);
}
__device__ __forceinline__ void ffma2(unsigned long long& d, unsigned long long a,
                                      unsigned long long b) {
    asm("fma.rn.f32x2 %0, %1, %2, %0;" : "+l"(d) : "l"(a), "l"(b));
}
__device__ __forceinline__ float fcollapse(unsigned long long v) {
    float lo, hi;
    asm("mov.b64 {%0, %1}, %2;" : "=f"(lo), "=f"(hi) : "l"(v));
    return lo + hi;
}
__device__ __forceinline__ void cpa16(void* smem_dst, const void* gsrc) {
    unsigned sd = (unsigned)__cvta_generic_to_shared(smem_dst);
    asm volatile("cp.async.cg.shared.global [%0], [%1], 16;" :: "r"(sd), "l"(gsrc));
}
__device__ __forceinline__ void cpa_commit() {
    asm volatile("cp.async.commit_group;" ::: "memory");
}
__device__ __forceinline__ void cpa_wait0() {
    asm volatile("cp.async.wait_group 0;" ::: "memory");
}

// ---------------- init: h=0, amax encodes sos token -------------------------
__global__ void k_init(const int* __restrict__ sos_p) {
    int i = blockIdx.x * blockDim.x + threadIdx.x;
    if (i < B_SZ * DHID) g_h[i] = 0.0f;
    if (i < B_SZ) {
        int sos = *sos_p;
        g_amax[i] = (unsigned long long)(0x7FFFFFFFu - (unsigned int)sos);
    }
}

// ---------------- one-time: enc_proj[sb][a] = W1[a,512:]@enc[sb] + b1[a] ----
__global__ void k_encproj(const float* __restrict__ enc,
                          const float* __restrict__ W1,
                          const float* __restrict__ b1) {
    __shared__ float enc_sh[8 * E2D];
    int tid = threadIdx.x;
    int sb0 = blockIdx.x * 8;
    for (int i = tid; i < 8 * E2D; i += 256)
        enc_sh[i] = enc[sb0 * E2D + i];
    __syncthreads();
    int a = tid & 31;
    int r = tid >> 5;
    const float* w = W1 + a * CATD + DHID;
    const float* e = enc_sh + r * E2D;
    float a0 = 0.f, a1 = 0.f, a2 = 0.f, a3 = 0.f;
#pragma unroll 8
    for (int k = 0; k < E2D; k += 4) {
        a0 = fmaf(w[k],     e[k],     a0);
        a1 = fmaf(w[k + 1], e[k + 1], a1);
        a2 = fmaf(w[k + 2], e[k + 2], a2);
        a3 = fmaf(w[k + 3], e[k + 3], a3);
    }
    g_enc_proj[(sb0 + r) * AHID + a] = a0 + a1 + a2 + a3 + b1[a];
}

// =============================================================================
// k_estep: one launch doing three independent jobs (all depend only on g_h):
//   blocks [0,250)   : logits GEMM + fused argmax (k-pair f32x2, cp.async pipe)
//   blocks [250,298) : gh partial GEMM for NEXT step   (W_hh @ h -> g_ghp)
//   blocks [298,330) : attention + context for NEXT step (-> g_ctx)
// =============================================================================
// shared layout (logits role):
//   wo buffers: 2 x 128 rows x 36 floats  = 36864 B   [0, 36864)
//   h  buffers: 2 x  32 rows x 36 floats  =  9216 B   [36864, 46080)
//   out staging (reuses wo[0] region): 32 x 132 floats = 16896 B
#define LOG_WSTRIDE 36
#define LOG_WBUF    (128 * LOG_WSTRIDE)   // floats per wo buffer
#define LOG_HBUF    (32 * LOG_WSTRIDE)    // floats per h buffer
__global__ void __launch_bounds__(128) k_estep(
    const float* __restrict__ enc,
    const float* __restrict__ W1,
    const float* __restrict__ W2,
    const float* __restrict__ b2,
    const float* __restrict__ W_hh,
    const float* __restrict__ Wo,
    const float* __restrict__ bo,
    float* __restrict__ out_t) {
    __shared__ __align__(16) float sm[2 * LOG_WBUF + 2 * LOG_HBUF];  // 46080 B
    __shared__ unsigned long long bmax[B_SZ];
    int tid = threadIdx.x;
    int bk = blockIdx.x;

    if (bk < 250) {
        // ---- logits: D[b][v] = h[b] . Wo[v] + bo[v], f32x2 packed over k ----
        if (out_t == nullptr) return;
        int v0 = bk * 128;
        float* wo_s = sm;                       // [buf][v][k] stride 36
        float* h_s  = sm + 2 * LOG_WBUF;        // [buf][b][k] stride 36
        int w  = tid >> 5;
        int tx = tid & 31;
        int vg = w & 1;                          // v half (64)
        int bg = w >> 1;                         // b half (16)
        int vsub = tx >> 2;                      // 0..7
        int bsub = tx & 3;                       // 0..3
        if (tid < B_SZ) bmax[tid] = 0ull;

        unsigned long long acc[8][4];
#pragma unroll
        for (int j = 0; j < 8; j++)
#pragma unroll
            for (int m = 0; m < 4; m++) acc[j][m] = 0ull;

        // prefetch chunk 0
        {
            float* wd = wo_s;  float* hd = h_s;
#pragma unroll
            for (int j = 0; j < 8; j++) {
                int gid = tid + 128 * j;          // granule id
                int v = gid >> 3, g16 = gid & 7;
                cpa16(wd + v * LOG_WSTRIDE + g16 * 4,
                      Wo + (size_t)(v0 + v) * DHID + g16 * 4);
            }
#pragma unroll
            for (int j = 0; j < 2; j++) {
                int gid = tid + 128 * j;
                int b = gid >> 3, g16 = gid & 7;
                cpa16(hd + b * LOG_WSTRIDE + g16 * 4,
                      g_h + b * DHID + g16 * 4);
            }
            cpa_commit();
        }

        for (int c = 0; c < 16; c++) {
            cpa_wait0();
            __syncthreads();
            if (c < 15) {
                int kc = (c + 1) * 32;
                float* wd = wo_s + ((c + 1) & 1) * LOG_WBUF;
                float* hd = h_s + ((c + 1) & 1) * LOG_HBUF;
#pragma unroll
                for (int j = 0; j < 8; j++) {
                    int gid = tid + 128 * j;
                    int v = gid >> 3, g16 = gid & 7;
                    cpa16(wd + v * LOG_WSTRIDE + g16 * 4,
                          Wo + (size_t)(v0 + v) * DHID + kc + g16 * 4);
                }
#pragma unroll
                for (int j = 0; j < 2; j++) {
                    int gid = tid + 128 * j;
                    int b = gid >> 3, g16 = gid & 7;
                    cpa16(hd + b * LOG_WSTRIDE + g16 * 4,
                          g_h + b * DHID + kc + g16 * 4);
                }
                cpa_commit();
            }
            const float* wb = wo_s + (c & 1) * LOG_WBUF + vg * 64 * LOG_WSTRIDE
                              + vsub * LOG_WSTRIDE;
            const float* hb = h_s + (c & 1) * LOG_HBUF + bg * 16 * LOG_WSTRIDE
                              + bsub * LOG_WSTRIDE;
#pragma unroll
            for (int g = 0; g < 8; g++) {       // 4 k per group (2 pairs)
                ulonglong2 wq[8];
#pragma unroll
                for (int j = 0; j < 8; j++)
                    wq[j] = *reinterpret_cast<const ulonglong2*>(
                        wb + j * 8 * LOG_WSTRIDE + g * 4);
                ulonglong2 hq[4];
#pragma unroll
                for (int m = 0; m < 4; m++)
                    hq[m] = *reinterpret_cast<const ulonglong2*>(
                        hb + m * 4 * LOG_WSTRIDE + g * 4);
#pragma unroll
                for (int j = 0; j < 8; j++)
#pragma unroll
                    for (int m = 0; m < 4; m++) {
                        ffma2(acc[j][m], wq[j].x, hq[m].x);
                        ffma2(acc[j][m], wq[j].y, hq[m].y);
                    }
            }
        }

        // stage results to smem (reuse wo buffer region), layout st[b][v] s132
        __syncthreads();
        float* st = sm;
#pragma unroll
        for (int j = 0; j < 8; j++) {
            int v = vg * 64 + vsub + 8 * j;
#pragma unroll
            for (int m = 0; m < 4; m++) {
                int b = bg * 16 + bsub + 4 * m;
                st[b * 132 + v] = fcollapse(acc[j][m]);
            }
        }
        __syncthreads();

        // coalesced write-out + argmax: thread handles 32 consecutive v of row b
        {
            int b = tid >> 2, q = tid & 3;
            int vbase = v0 + q * 32;
            const float* srow = st + b * 132 + q * 32;
            float best = -3.4e38f; int bi = 0;
            float vals[32];
#pragma unroll
            for (int i = 0; i < 32; i++) {
                float x = srow[i] + bo[vbase + i];
                vals[i] = x;
                if (x > best) { best = x; bi = vbase + i; }
            }
            float* orow = out_t + (size_t)b * VOCAB + vbase;
#pragma unroll
            for (int i = 0; i < 8; i++) {
                float4 v4 = make_float4(vals[4 * i], vals[4 * i + 1],
                                        vals[4 * i + 2], vals[4 * i + 3]);
                __stcs(reinterpret_cast<float4*>(orow + 4 * i), v4);
            }
            atomicMax(&bmax[b], packkey(best, bi));
        }
        __syncthreads();
        if (tid < B_SZ) atomicMax(&g_amax[tid], bmax[tid]);
        return;
    }

    if (bk < 298) {
        // ---- gh partial: tile 128o x 32b, K range [c*128, c*128+128) -------
        int r = bk - 250;
        int c = r & 3, ot = r >> 2;
        int o0 = ot * 128, kc0 = c * 128;
        float* w_s = sm;              // [k][o] stride 129 (4128 floats)
        float* x_s = sm + 4128;       // [k][b] stride 33
        int tk = tid & 31, tg = tid >> 5;
        int tx = tid & 31, ty = tid >> 5;
        float acc[4][8] = {};
        float pw[32], ph[8];
#pragma unroll
        for (int j = 0; j < 32; j++)
            pw[j] = W_hh[(o0 + tg + 4 * j) * DHID + kc0 + tk];
#pragma unroll
        for (int j = 0; j < 8; j++)
            ph[j] = g_h[(tg + 4 * j) * DHID + kc0 + tk];
        for (int kc = kc0; kc < kc0 + 128; kc += 32) {
            __syncthreads();
#pragma unroll
            for (int j = 0; j < 32; j++) w_s[tk * 129 + tg + 4 * j] = pw[j];
#pragma unroll
            for (int j = 0; j < 8; j++)  x_s[tk * 33 + tg + 4 * j] = ph[j];
            __syncthreads();
            if (kc + 32 < kc0 + 128) {
#pragma unroll
                for (int j = 0; j < 32; j++)
                    pw[j] = W_hh[(o0 + tg + 4 * j) * DHID + kc + 32 + tk];
#pragma unroll
                for (int j = 0; j < 8; j++)
                    ph[j] = g_h[(tg + 4 * j) * DHID + kc + 32 + tk];
            }
#pragma unroll 4
            for (int k = 0; k < 32; k++) {
                const float* wr = &w_s[k * 129 + tx];
                float w0 = wr[0], w1 = wr[32], w2 = wr[64], w3 = wr[96];
                const float* hr = &x_s[k * 33 + ty * 8];
#pragma unroll
                for (int bj = 0; bj < 8; bj++) {
                    float hb = hr[bj];
                    acc[0][bj] = fmaf(w0, hb, acc[0][bj]);
                    acc[1][bj] = fmaf(w1, hb, acc[1][bj]);
                    acc[2][bj] = fmaf(w2, hb, acc[2][bj]);
                    acc[3][bj] = fmaf(w3, hb, acc[3][bj]);
                }
            }
        }
#pragma unroll
        for (int vi = 0; vi < 4; vi++)
#pragma unroll
            for (int bj = 0; bj < 8; bj++)
                g_ghp[(c * 3 * DHID + o0 + tx + vi * 32) * B_SZ + ty * 8 + bj] = acc[vi][bj];
        return;
    }

    // ---- attention for next step, one block per batch ----------------------
    {
        int b = bk - 298;
        float* h_sh  = sm;         // 512
        float* part  = sm + 512;   // 4*32
        float* hproj = sm + 640;   // 32
        float* sc    = sm + 672;   // 128
        float* red   = sm + 800;   // 2
        for (int i = tid; i < DHID; i += 128) h_sh[i] = g_h[b * DHID + i];
        __syncthreads();
        {   // hproj[a] = W1[a,0:512] @ h : 4 segments of 128
            int a = tid & 31, seg = tid >> 5;
            const float* w  = W1 + a * CATD + seg * 128;
            const float* hh = h_sh + seg * 128;
            float acc = 0.f;
#pragma unroll 8
            for (int k = 0; k < 128; k++) acc = fmaf(w[k], hh[k], acc);
            part[seg * 32 + a] = acc;
        }
        __syncthreads();
        if (tid < AHID)
            hproj[tid] = part[tid] + part[32 + tid] + part[64 + tid] + part[96 + tid];
        __syncthreads();
        {   // scores over S (one thread per s)
            int s = tid;
            const float* ep = g_enc_proj + (s * B_SZ + b) * AHID;
            float sv = b2[0];
#pragma unroll
            for (int a = 0; a < AHID; a++) {
                float t = ep[a] + hproj[a];
                sv = fmaf(W2[a], fmaxf(t, 0.f), sv);
            }
            sc[s] = sv;
        }
        __syncthreads();
        if (tid < 32) {
            float m = fmaxf(fmaxf(sc[tid], sc[tid + 32]), fmaxf(sc[tid + 64], sc[tid + 96]));
#pragma unroll
            for (int off = 16; off > 0; off >>= 1)
                m = fmaxf(m, __shfl_xor_sync(0xffffffffu, m, off));
            if (tid == 0) red[0] = m;
        }
        __syncthreads();
        sc[tid] = expf(sc[tid] - red[0]);
        __syncthreads();
        if (tid < 32) {
            float s4 = sc[tid] + sc[tid + 32] + sc[tid + 64] + sc[tid + 96];
#pragma unroll
            for (int off = 16; off > 0; off >>= 1)
                s4 += __shfl_xor_sync(0xffffffffu, s4, off);
            if (tid == 0) red[1] = 1.0f / s4;
        }
        __syncthreads();
        sc[tid] *= red[1];
        __syncthreads();
        {   // context: each thread 8 consecutive e
            float acc[8] = {};
            const float4* e4 = reinterpret_cast<const float4*>(enc);
#pragma unroll 4
            for (int s = 0; s < S_LEN; s++) {
                float a = sc[s];
                int base4 = ((s * B_SZ + b) * E2D + tid * 8) >> 2;
                float4 v0 = e4[base4], v1 = e4[base4 + 1];
                acc[0] = fmaf(a, v0.x, acc[0]); acc[1] = fmaf(a, v0.y, acc[1]);
                acc[2] = fmaf(a, v0.z, acc[2]); acc[3] = fmaf(a, v0.w, acc[3]);
                acc[4] = fmaf(a, v1.x, acc[4]); acc[5] = fmaf(a, v1.y, acc[5]);
                acc[6] = fmaf(a, v1.z, acc[6]); acc[7] = fmaf(a, v1.w, acc[7]);
            }
            float* dst = g_ctx + b * E2D + tid * 8;
#pragma unroll
            for (int j = 0; j < 8; j++) dst[j] = acc[j];
        }
    }
}

// ---------------- gi partial GEMM (x = [ctx | emb[argmax]]) -----------------
// grid 240 blocks (24 o-tiles of 64 x 10 K-splits), 128 threads
__global__ void __launch_bounds__(128) k_gigemm(const float* __restrict__ W_ih,
                                                const float* __restrict__ emb) {
    __shared__ __align__(16) float w_s[32 * 65];
    __shared__ float x_s[32 * 33];
    __shared__ int sh_id[B_SZ];
    int tid = threadIdx.x;
    int ot = blockIdx.x % 24, sp = blockIdx.x / 24;
    int o0 = ot * 64, kc0 = sp * 128;
    int tk = tid & 31, tg = tid >> 5;
    if (tid < B_SZ) {
        unsigned long long p = g_amax[tid];
        sh_id[tid] = (int)(0x7FFFFFFFu - (unsigned int)(p & 0x7FFFFFFFull));
    }
    __syncthreads();
    int tx = tid & 31, ty = tid >> 5;
    bool is_ctx = (kc0 < E2D);
    float acc[2][8] = {};
    float pw[16], px[8];
#pragma unroll
    for (int j = 0; j < 16; j++)
        pw[j] = W_ih[(o0 + tg + 4 * j) * XDIM + kc0 + tk];
#pragma unroll
    for (int j = 0; j < 8; j++) {
        int b = tg + 4 * j, kg = kc0 + tk;
        px[j] = is_ctx ? g_ctx[b * E2D + kg]
                       : emb[(size_t)sh_id[b] * EMBD + (kg - E2D)];
    }
    for (int kc = kc0; kc < kc0 + 128; kc += 32) {
        __syncthreads();
#pragma unroll
        for (int j = 0; j < 16; j++) w_s[tk * 65 + tg + 4 * j] = pw[j];
#pragma unroll
        for (int j = 0; j < 8; j++)  x_s[tk * 33 + tg + 4 * j] = px[j];
        __syncthreads();
        if (kc + 32 < kc0 + 128) {
#pragma unroll
            for (int j = 0; j < 16; j++)
                pw[j] = W_ih[(o0 + tg + 4 * j) * XDIM + kc + 32 + tk];
#pragma unroll
            for (int j = 0; j < 8; j++) {
                int b = tg + 4 * j, kg = kc + 32 + tk;
                px[j] = is_ctx ? g_ctx[b * E2D + kg]
                               : emb[(size_t)sh_id[b] * EMBD + (kg - E2D)];
            }
        }
#pragma unroll 4
        for (int k = 0; k < 32; k++) {
            const float* wr = &w_s[k * 65 + tx];
            float w0 = wr[0], w1 = wr[32];
            const float* hr = &x_s[k * 33 + ty * 8];
#pragma unroll
            for (int bj = 0; bj < 8; bj++) {
                float hb = hr[bj];
                acc[0][bj] = fmaf(w0, hb, acc[0][bj]);
                acc[1][bj] = fmaf(w1, hb, acc[1][bj]);
            }
        }
    }
#pragma unroll
    for (int vi = 0; vi < 2; vi++)
#pragma unroll
        for (int bj = 0; bj < 8; bj++)
            g_gip[(sp * 3 * DHID + o0 + tx + vi * 32) * B_SZ + ty * 8 + bj] = acc[vi][bj];
}

// ---------------- GRU elementwise: sum partials, gates, h_new ---------------
__global__ void __launch_bounds__(128) k_gruelem(const float* __restrict__ b_ih,
                                                 const float* __restrict__ b_hh) {
    int i = blockIdx.x * blockDim.x + threadIdx.x;
    if (i >= B_SZ * DHID) return;
    int b = i & 31, d = i >> 5;
    float gr = 0.f, gz = 0.f, gn = 0.f;
#pragma unroll
    for (int sp = 0; sp < NSPI; sp++) {
        int base = (sp * 3 * DHID + d) * B_SZ + b;
        gr += g_gip[base];
        gz += g_gip[base + DHID * B_SZ];
        gn += g_gip[base + 2 * DHID * B_SZ];
    }
    float hr = 0.f, hz = 0.f, hn = 0.f;
#pragma unroll
    for (int c = 0; c < NSPH; c++) {
        int base = (c * 3 * DHID + d) * B_SZ + b;
        hr += g_ghp[base];
        hz += g_ghp[base + DHID * B_SZ];
        hn += g_ghp[base + 2 * DHID * B_SZ];
    }
    float gir = gr + hr + b_ih[d] + b_hh[d];
    float giz = gz + hz + b_ih[DHID + d] + b_hh[DHID + d];
    float gin = gn + b_ih[2 * DHID + d];
    float ghn = hn + b_hh[2 * DHID + d];
    float r = 1.f / (1.f + expf(-gir));
    float z = 1.f / (1.f + expf(-giz));
    float n = tanhf(fmaf(r, ghn, gin));
    float ho = g_h[b * DHID + d];
    g_h[b * DHID + d] = fmaf(z, ho - n, n);
    if (i < B_SZ) g_amax[i] = 0ull;   // reset before this step's logits atomics
}

// ---------------- launch ----------------------------------------------------
extern "C" void kernel_launch(void* const* d_in, const int* in_sizes, int n_in,
                              void* d_out, int out_size) {
    const float* enc   = (const float*)d_in[0];
    const int*   sos_p = (const int*)  d_in[2];
    const float* emb   = (const float*)d_in[3];
    const float* W1    = (const float*)d_in[4];
    const float* b1    = (const float*)d_in[5];
    const float* W2    = (const float*)d_in[6];
    const float* b2    = (const float*)d_in[7];
    const float* W_ih  = (const float*)d_in[8];
    const float* b_ih  = (const float*)d_in[9];
    const float* W_hh  = (const float*)d_in[10];
    const float* b_hh  = (const float*)d_in[11];
    const float* Wo    = (const float*)d_in[12];
    const float* bo    = (const float*)d_in[13];
    float* out = (float*)d_out;

    int T = out_size / (B_SZ * VOCAB);

    k_init<<<64, 256>>>(sos_p);
    k_encproj<<<S_LEN * B_SZ / 8, 256>>>(enc, W1, b1);
    // prologue: attn(0) + gh(0), no logits
    k_estep<<<330, 128>>>(enc, W1, W2, b2, W_hh, Wo, bo, nullptr);

    for (int t = 0; t < T; t++) {
        k_gigemm<<<240, 128>>>(W_ih, emb);
        k_gruelem<<<128, 128>>>(b_ih, b_hh);
        // logits(t) + attn(t+1) + gh(t+1)  (the t=T-1 extras are harmless)
        k_estep<<<330, 128>>>(enc, W1, W2, b2, W_hh, Wo, bo,
                              out + (size_t)t * B_SZ * VOCAB);
    }
}